// round 12
// baseline (speedup 1.0000x reference)
#include <cuda_runtime.h>
#include <cuda_fp16.h>

// ---------------- problem constants ----------------
#define MM    128            // n_mels
#define FF    1025           // n_stft
#define FPc   1088           // padded F
#define SSTR  1104           // staging stride (floats): %32==16
#define HSTR  1104           // spec16 stride (halves): mult of 4
#define DSTR  144            // mel stride (floats)
#define D2STR 264            // diff2 stride (floats; 132 float2)
#define TT    1024
#define NITER 20
#define LRc   0.3f
#define MOMc  0.9f
#define INVc  (2.0f / 4096.0f)

#define ROWS  16             // rows per CTA
#define NTHR  256
#define NCTA  256            // 256*16 = 4096; two clean waves on 148 SMs
#define NJ    17             // phase C steps: 17 * 64 f = 1088
#define NC4M  12             // 4-slot chunks per mel (48 >= max width ~46)

// ---------------- persistent table scratch ----------------
__device__ __half2 g_w01h[FPc];        // (w0, w1) per bin, fp16
__device__ unsigned char g_i0[FPc];    // clamped first mel index (<=126)
__device__ uint2   g_csrh[NC4M*MM];    // chunk-major: 4 fp16 weights per chunk per mel
__device__ int     g_lo[MM];           // aligned lo (multiple of 4)
__device__ int     g_nc4[MM];          // chunks per mel (<= NC4M)

// ---------------- merged prep kernel (unchanged from R10) ----------------
__global__ void prep_kernel(const float* __restrict__ fb) {
    const int blk = blockIdx.x;
    if (blk < 272) {
        const int warp = threadIdx.x >> 5;
        const int lane = threadIdx.x & 31;
        const int f = blk * 4 + warp;
        if (f >= FF) {
            if (f < FPc && lane == 0) { g_w01h[f] = __floats2half2_rn(0.f, 0.f); g_i0[f] = 0; }
            return;
        }
        const float* fr = fb + f * MM;
        unsigned b0 = __ballot_sync(0xffffffffu, fr[lane]      > 0.f);
        unsigned b1 = __ballot_sync(0xffffffffu, fr[lane + 32] > 0.f);
        unsigned b2 = __ballot_sync(0xffffffffu, fr[lane + 64] > 0.f);
        unsigned b3 = __ballot_sync(0xffffffffu, fr[lane + 96] > 0.f);
        if (lane == 0) {
            int fm = b0 ? (__ffs(b0) - 1)
                   : b1 ? (32 + __ffs(b1) - 1)
                   : b2 ? (64 + __ffs(b2) - 1)
                   : b3 ? (96 + __ffs(b3) - 1) : -1;
            if (fm < 0) {
                g_w01h[f] = __floats2half2_rn(0.f, 0.f); g_i0[f] = 0;
            } else {
                int i0 = fm > 126 ? 126 : fm;
                g_w01h[f] = __floats2half2_rn(fr[i0], fr[i0 + 1]);
                g_i0[f]   = (unsigned char)i0;
            }
        }
    } else {
        __shared__ int s_mn[128], s_mx[128];
        const int m = blk - 272;
        const int t = threadIdx.x;
        int mn = FF, mx = -1;
        for (int f = t; f < FF; f += 128) {
            if (fb[f * MM + m] > 0.f) { mn = min(mn, f); mx = max(mx, f); }
        }
        s_mn[t] = mn; s_mx[t] = mx;
        __syncthreads();
        for (int s = 64; s > 0; s >>= 1) {
            if (t < s) { s_mn[t] = min(s_mn[t], s_mn[t + s]); s_mx[t] = max(s_mx[t], s_mx[t + s]); }
            __syncthreads();
        }
        const int lo_al = (s_mx[0] < 0) ? 0 : (s_mn[0] & ~3);
        int cnt = (s_mx[0] < 0) ? 0 : (s_mx[0] + 1 - lo_al);
        int cnt_al = (cnt + 3) & ~3;
        if (cnt_al > 4 * NC4M) cnt_al = 4 * NC4M;
        if (t == 0) { g_lo[m] = lo_al; g_nc4[m] = cnt_al >> 2; }
        if (t < 4 * NC4M) {
            float w = (lo_al + t < FF) ? fb[(lo_al + t) * MM + m] : 0.f;
            reinterpret_cast<__half*>(g_csrh)[((t >> 2) * MM + m) * 4 + (t & 3)] = __float2half(w);
        }
    }
}

// ---------------- SMEM layout (float offsets) ----------------
#define OFF_STAGE 0                                  // fp32 staging: 16*1104 = 17664
#define OFF_SP16  (OFF_STAGE + ROWS * SSTR)          // 17664: fp16 spec shadow (8832 floats)
#define OFF_MEL   (OFF_SP16  + ROWS * HSTR / 2)      // 26496
#define OFF_D2    (OFF_MEL   + ROWS * DSTR)          // 28800
#define OFF_W01H  (OFF_D2    + ROWS * D2STR)         // 33024 (16B aligned)
#define OFF_CSR   (OFF_W01H  + FPc)                  // 34112 (8B aligned)
#define OFF_LONC  (OFF_CSR   + 2 * NC4M * MM)        // 37184
#define OFF_I0    (OFF_LONC  + MM)                   // 37312
#define SM_FLOATS (OFF_I0 + FPc / 4)                 // 37584 floats = 150336 B

// ---------------- main persistent kernel ----------------
__global__ __launch_bounds__(NTHR, 1)
void invmel_kernel(const float* __restrict__ melspec,
                   const float* __restrict__ spec_init,
                   float* __restrict__ out) {
    extern __shared__ float smem[];
    float*  s_stage = smem + OFF_STAGE;
    __half* s_sp16  = reinterpret_cast<__half*>(smem + OFF_SP16);
    float*  s_mel   = smem + OFF_MEL;
    float*  s_d2f   = smem + OFF_D2;
    float2* s_d2    = reinterpret_cast<float2*>(s_d2f);
    unsigned int* s_w01h = reinterpret_cast<unsigned int*>(smem + OFF_W01H);
    uint2*  s_csr2  = reinterpret_cast<uint2*>(smem + OFF_CSR);
    int*    s_lonc  = reinterpret_cast<int*>(smem + OFF_LONC);
    unsigned char* s_i0 = reinterpret_cast<unsigned char*>(smem + OFF_I0);

    const int tid  = threadIdx.x;
    const int row0 = blockIdx.x * ROWS;

    // ---- tables ----
    for (int i = tid; i < FPc; i += NTHR) {
        s_w01h[i] = reinterpret_cast<const unsigned int*>(g_w01h)[i];
        s_i0[i]   = g_i0[i];
    }
    for (int i = tid; i < NC4M * MM; i += NTHR) s_csr2[i] = g_csrh[i];
    if (tid < MM) s_lonc[tid] = g_lo[tid] | (g_nc4[tid] << 16);

    // ---- fp32 spec -> staging (coalesced over f; pad [FF,FPc) with 0) ----
    for (int i = tid; i < ROWS * FPc; i += NTHR) {
        const int r = i / FPc;
        const int f = i - r * FPc;
        s_stage[r * SSTR + f] = (f < FF) ? spec_init[(size_t)(row0 + r) * FF + f] : 0.f;
    }
    // ---- mel tile (fp32) ----
    for (int i = tid; i < ROWS * MM; i += NTHR) {
        const int m = i >> 4;
        const int r = i & 15;
        const int g = row0 + r;
        const int b = g >> 10;
        const int t = g & 1023;
        s_mel[r * DSTR + m] = melspec[((size_t)b * MM + m) * TT + t];
    }
    __syncthreads();

    // ---- build fp16 shadow from staging ----
    for (int i = tid; i < ROWS * FPc; i += NTHR) {
        const int r = i / FPc;
        const int f = i - r * FPc;
        s_sp16[r * HSTR + f] = __float2half(s_stage[r * SSTR + f]);
    }

    // ---- roles: half-warp per row; lane owns f = 64j+4q..+3 ----
    const int row    = tid >> 4;   // 0..15 (all active)
    const int q      = tid & 15;
    const int dbase  = row * DSTR;
    const int d2base = row * (D2STR / 2);
    __half* const sp16row = s_sp16 + row * HSTR;

    // spec master in registers
    float4 spec[NJ];
    #pragma unroll
    for (int j = 0; j < NJ; ++j)
        spec[j] = *reinterpret_cast<const float4*>(s_stage + row * SSTR + 64 * j + 4 * q);

    int lonc[8];
    #pragma unroll
    for (int j = 0; j < 8; ++j) lonc[j] = s_lonc[16 * j + q];

    float4 buf[NJ];
    #pragma unroll
    for (int j = 0; j < NJ; ++j) buf[j] = make_float4(0.f, 0.f, 0.f, 0.f);

    __syncthreads();   // spec16 fully built before phase A reads it

    for (int it = 0; it < NITER; ++it) {
        // ======== phase A: d[m] = mel[m] - sum_k w16(m,k)*spec16[lo+k] ========
        #pragma unroll
        for (int j = 0; j < 8; ++j) {
            const int m  = 16 * j + q;
            const int lo = lonc[j] & 0xffff;
            const int n  = lonc[j] >> 16;
            const uint2* __restrict__ cw  = s_csr2 + m;
            const uint2* __restrict__ sp2 = reinterpret_cast<const uint2*>(sp16row + lo);
            float a0 = 0.f, a1 = 0.f;
            #pragma unroll 2
            for (int c = 0; c < n; ++c) {
                const uint2 wr = cw[c * MM];
                const uint2 sr = sp2[c];
                const float2 w0 = __half22float2(*reinterpret_cast<const __half2*>(&wr.x));
                const float2 w1 = __half22float2(*reinterpret_cast<const __half2*>(&wr.y));
                const float2 s0 = __half22float2(*reinterpret_cast<const __half2*>(&sr.x));
                const float2 s1 = __half22float2(*reinterpret_cast<const __half2*>(&sr.y));
                a0 = fmaf(w0.x, s0.x, a0);
                a1 = fmaf(w0.y, s0.y, a1);
                a0 = fmaf(w1.x, s1.x, a0);
                a1 = fmaf(w1.y, s1.y, a1);
            }
            float d = s_mel[dbase + m] - (a0 + a1);
            float dn = __shfl_down_sync(0xffffffffu, d, 1);
            if (j == 7 && q == 15) dn = 0.f;            // d[128] pad
            *reinterpret_cast<float2*>(s_d2f + row * D2STR + 2 * m) = make_float2(d, dn);
            if (j > 0 && q == 0)
                s_d2f[row * D2STR + 2 * m - 1] = d;     // fix previous group's q=15 .y slot
        }
        __syncwarp();

        // ======== phase C: regs spec/buf; dot = w0*d0 + w1*d1; store fp16 shadow ========
        #pragma unroll
        for (int j = 0; j < NJ; ++j) {
            const int f = 64 * j + 4 * q;
            const uint4 wr = *reinterpret_cast<const uint4*>(s_w01h + f);
            const uchar4 ii = *reinterpret_cast<const uchar4*>(s_i0 + f);
            const float2 wA = __half22float2(*reinterpret_cast<const __half2*>(&wr.x));
            const float2 wB = __half22float2(*reinterpret_cast<const __half2*>(&wr.y));
            const float2 wC = __half22float2(*reinterpret_cast<const __half2*>(&wr.z));
            const float2 wD = __half22float2(*reinterpret_cast<const __half2*>(&wr.w));
            const float2 dA = s_d2[d2base + ii.x];
            const float2 dB = s_d2[d2base + ii.y];
            const float2 dC = s_d2[d2base + ii.z];
            const float2 dD = s_d2[d2base + ii.w];
            const float dot0 = fmaf(wA.x, dA.x, wA.y * dA.y);
            const float dot1 = fmaf(wB.x, dB.x, wB.y * dB.y);
            const float dot2 = fmaf(wC.x, dC.x, wC.y * dC.y);
            const float dot3 = fmaf(wD.x, dD.x, wD.y * dD.y);
            float4 bv;
            bv.x = fmaf(MOMc, buf[j].x, -INVc * dot0);
            bv.y = fmaf(MOMc, buf[j].y, -INVc * dot1);
            bv.z = fmaf(MOMc, buf[j].z, -INVc * dot2);
            bv.w = fmaf(MOMc, buf[j].w, -INVc * dot3);
            buf[j] = bv;
            float4 sp = spec[j];
            sp.x = fmaxf(fmaf(-LRc, bv.x, sp.x), 0.f);
            sp.y = fmaxf(fmaf(-LRc, bv.y, sp.y), 0.f);
            sp.z = fmaxf(fmaf(-LRc, bv.z, sp.z), 0.f);
            sp.w = fmaxf(fmaf(-LRc, bv.w, sp.w), 0.f);
            spec[j] = sp;
            // fp16 shadow store (half4 = uint2)
            uint2 h;
            *reinterpret_cast<__half2*>(&h.x) = __floats2half2_rn(sp.x, sp.y);
            *reinterpret_cast<__half2*>(&h.y) = __floats2half2_rn(sp.z, sp.w);
            *reinterpret_cast<uint2*>(sp16row + f) = h;
        }
        __syncwarp();
    }

    // ---- regs -> staging ----
    #pragma unroll
    for (int j = 0; j < NJ; ++j)
        *reinterpret_cast<float4*>(s_stage + row * SSTR + 64 * j + 4 * q) = spec[j];
    __syncthreads();

    // ---- epilogue: out[b][f][t] = stage[r][f]; 4-row float4 groups (batch-pure) ----
    for (int f = tid; f < FF; f += NTHR) {
        const float* __restrict__ spp = s_stage + f;
        #pragma unroll 2
        for (int r = 0; r < ROWS; r += 4) {
            const int g = row0 + r;           // multiple of 4; group shares batch
            const int b = g >> 10;
            const int t = g & 1023;
            float4 v;
            v.x = spp[(r + 0) * SSTR];
            v.y = spp[(r + 1) * SSTR];
            v.z = spp[(r + 2) * SSTR];
            v.w = spp[(r + 3) * SSTR];
            *reinterpret_cast<float4*>(out + ((size_t)b * FF + f) * TT + t) = v;
        }
    }
}

// ---------------- launch ----------------
extern "C" void kernel_launch(void* const* d_in, const int* in_sizes, int n_in,
                              void* d_out, int out_size) {
    const float* melspec   = (const float*)d_in[0];  // (4,128,1024)
    const float* spec_init = (const float*)d_in[1];  // (4,1024,1025)
    const float* fb        = (const float*)d_in[2];  // (1025,128)
    float* out             = (float*)d_out;          // (4,1025,1024)

    const int smem_bytes = SM_FLOATS * sizeof(float);   // 150336
    cudaFuncSetAttribute(invmel_kernel, cudaFuncAttributeMaxDynamicSharedMemorySize, smem_bytes);

    prep_kernel<<<400, 128>>>(fb);
    invmel_kernel<<<NCTA, NTHR, smem_bytes>>>(melspec, spec_init, out);
}